// round 7
// baseline (speedup 1.0000x reference)
#include <cuda_runtime.h>
#include <math.h>

// ---------------- problem constants ----------------
constexpr int   B_TOT  = 1000000;
constexpr int   SPIN   = 1000;
constexpr int   TRAIN  = 800000;
constexpr float ML     = 2.9086f;
constexpr float SL     = 1.898f;
constexpr float U1MAX  = 221.519f;

// chunked-scan parameters
constexpr int CHUNK  = 32;                    // steps per chunk
constexpr int WARMCH = 2;                     // warm-up chunks (64 steps)
constexpr int NCH    = B_TOT / CHUNK;         // 31250
constexpr int CPB    = 32;                    // chunks per block (= 1 scan warp)
constexpr int SBLK   = 256;                   // threads per block
constexpr int GRID   = (NCH + CPB - 1) / CPB; // 977
constexpr int ROWS   = CPB + WARMCH;          // 34 window rows

constexpr int RBLOCKS = 132;
__device__ double g_part[RBLOCKS][2];

// dynamic SMEM layout (floats/float2s, stride 33 => conflict-free columns)
constexpr int SX_BYTES = ROWS * 33 * 8;            // 8976
constexpr int SG_BYTES = CPB * 33 * 4;             // 4224 per gate array
constexpr int SMEM_TOTAL = SX_BYTES + 5 * SG_BYTES; // 30096

// ---------------- math helpers ----------------
__device__ __forceinline__ float tanha(float z) {
    float r;
    asm("tanh.approx.f32 %0, %1;" : "=f"(r) : "f"(z));
    return r;
}

struct P {
    float koo, coo;        // zo = koo*c + coo
    float kib, cib, kibu;  // zi = kib*c + (kibu*u1 + cib)
    float kol, col;        // zl = kol*u2 + col
    float hoo1, hol1;      // 0.5*oo1, 0.5*ol1
};

__device__ __forceinline__ P load_params(
    const float* cmean, const float* cstd,
    const float* wro, const float* wrl, const float* wrf,
    const float* b0o, const float* wb1o,
    const float* b0l, const float* wb2l,
    const float* wb1u, const float* b0u)
{
    P p;
    float mo = cmean[0];
    float inv_so = 1.0f / cstd[0];
    float eo = __expf(wro[0]);
    float el = __expf(wrl[0]);
    float ef = __expf(wrf[0]);
    float id = __fdividef(1.0f, eo + el + ef);
    p.hoo1 = 0.5f * eo * id;
    p.hol1 = 0.5f * el * id;
    float w1o = wb1o[0], w1u = wb1u[0], w2l = wb2l[0];
    p.koo  = 0.5f * w1o * inv_so;
    p.coo  = 0.5f * (b0o[0] - mo * inv_so * w1o);
    p.kib  = 0.5f * w1u * inv_so;
    p.cib  = 0.5f * (b0u[0] - mo * inv_so * w1u);
    p.kibu = 0.5f * w1u / U1MAX;
    p.kol  = 0.5f * w2l / SL;
    p.col  = 0.5f * (b0l[0] - (ML / SL) * w2l);
    return p;
}

// warm-up step (state only). chain: fma -> tanh -> fma -> fma.
__device__ __forceinline__ float step_c(float c, float u1, float u2, const P& p) {
    float hu1 = 0.5f * u1;
    float zib = fmaf(u1, p.kibu, p.cib);
    float zl  = fmaf(u2, p.kol, p.col);
    float ol  = fmaf(tanha(zl), p.hol1, p.hol1);
    float zo  = fmaf(c, p.koo, p.coo);
    float zi  = fmaf(c, p.kib, zib);
    float to  = tanha(zo);
    float ti  = tanha(zi);
    float hc  = p.hoo1 * c;
    float olc_c = ol * c;
    float L   = (c > 0.0f) ? fminf(olc_c, u2) : olc_c;
    float base = ((c - hc) + hu1) - L;
    return fmaf(-hu1, ti, fmaf(-hc, to, base));
}

// ---------------- kernel A: sum/sumsq partials over y_obs[SPIN:TRAIN] -----
__global__ __launch_bounds__(256) void reduce_k(const float* __restrict__ y) {
    const float4* y4 = reinterpret_cast<const float4*>(y + SPIN);
    const int n4 = (TRAIN - SPIN) / 4;
    double s = 0.0, s2 = 0.0;
    int stride = gridDim.x * blockDim.x;
    for (int i = blockIdx.x * blockDim.x + threadIdx.x; i < n4; i += stride) {
        float4 v = __ldg(y4 + i);
        double a = v.x, b = v.y, cc = v.z, d = v.w;
        s  += (a + b) + (cc + d);
        s2 += (a * a + b * b) + (cc * cc + d * d);
    }
    #pragma unroll
    for (int o = 16; o > 0; o >>= 1) {
        s  += __shfl_down_sync(0xffffffffu, s,  o);
        s2 += __shfl_down_sync(0xffffffffu, s2, o);
    }
    __shared__ double sh[2][8];
    int lane = threadIdx.x & 31, warp = threadIdx.x >> 5;
    if (lane == 0) { sh[0][warp] = s; sh[1][warp] = s2; }
    __syncthreads();
    if (warp == 0) {
        s  = (lane < 8) ? sh[0][lane] : 0.0;
        s2 = (lane < 8) ? sh[1][lane] : 0.0;
        #pragma unroll
        for (int o = 4; o > 0; o >>= 1) {
            s  += __shfl_down_sync(0xffffffffu, s,  o);
            s2 += __shfl_down_sync(0xffffffffu, s2, o);
        }
        if (lane == 0) { g_part[blockIdx.x][0] = s; g_part[blockIdx.x][1] = s2; }
    }
}

// ---------------- kernel B: asymmetric fused scan + sweep -----------------
__global__ __launch_bounds__(SBLK, 4) void fused_k(
    const float4* __restrict__ x4,
    float* __restrict__ out,
    const int* __restrict__ time_lag_p,
    const float* cmean, const float* cstd,
    const float* wro, const float* wrl, const float* wrf,
    const float* b0o, const float* wb1o,
    const float* b0l, const float* wb2l,
    const float* wb1u, const float* b0u)
{
    extern __shared__ char smem_raw[];
    float2 (*sx)[33]   = reinterpret_cast<float2(*)[33]>(smem_raw);
    float  (*sc)[33]   = reinterpret_cast<float(*)[33]>(smem_raw + SX_BYTES);
    float  (*soo)[33]  = reinterpret_cast<float(*)[33]>(smem_raw + SX_BYTES + SG_BYTES);
    float  (*sib)[33]  = reinterpret_cast<float(*)[33]>(smem_raw + SX_BYTES + 2 * SG_BYTES);
    float  (*sol)[33]  = reinterpret_cast<float(*)[33]>(smem_raw + SX_BYTES + 3 * SG_BYTES);
    float  (*solc)[33] = reinterpret_cast<float(*)[33]>(smem_raw + SX_BYTES + 4 * SG_BYTES);
    __shared__ float s_os;

    const int tid  = threadIdx.x;
    const int warp = tid >> 5;
    const int lane = tid & 31;
    const int b0   = blockIdx.x * CPB;            // first chunk of this block
    const int base_t = (b0 - WARMCH) * CHUNK;     // window start (may be < 0)

    const P p = load_params(cmean, cstd, wro, wrl, wrf, b0o, wb1o, b0l, wb2l, wb1u, b0u);

    // ---- phase 1: warp 0 folds obsstd; warps 1-7 stage the input window ----
    if (warp == 0) {
        double s = 0.0, s2 = 0.0;
        for (int i = lane; i < RBLOCKS; i += 32) {
            s  += g_part[i][0];
            s2 += g_part[i][1];
        }
        #pragma unroll
        for (int o = 16; o > 0; o >>= 1) {
            s  += __shfl_down_sync(0xffffffffu, s,  o);
            s2 += __shfl_down_sync(0xffffffffu, s2, o);
        }
        if (lane == 0) {
            double n = (double)(TRAIN - SPIN);
            s_os = (float)sqrt((s2 - s * s / n) / (n - 1.0));
        }
    } else {
        constexpr int NLD4 = ROWS * CHUNK / 2;    // 544 float4 loads
        for (int i = tid - 32; i < NLD4; i += SBLK - 32) {
            int t = base_t + 2 * i;
            float4 v = make_float4(0.f, 0.f, 0.f, 0.f);
            if (t >= 0 && t < B_TOT) v = __ldg(x4 + (t >> 1));
            int li = 2 * i;
            int row = li >> 5, s = li & 31;
            sx[row][s]     = make_float2(v.x, v.y);
            sx[row][s + 1] = make_float2(v.z, v.w);
        }
    }
    __syncthreads();

    // ---- phase 2: one warp runs the recurrence for the block's 32 chunks ----
    const int wsel = blockIdx.x & 7;              // spread across SMSPs
    if (warp == wsel) {
        const int chunk = b0 + lane;
        if (chunk < NCH) {
            float c = 0.0f;
            #pragma unroll
            for (int d = WARMCH; d >= 1; --d) {
                if (chunk - d >= 0) {
                    const int row = lane + WARMCH - d;
                    #pragma unroll 8
                    for (int s = 0; s < CHUNK; ++s) {
                        float2 u = sx[row][s];
                        c = step_c(c, u.x, u.y, p);
                    }
                }
            }
            const int row = lane + WARMCH;
            #pragma unroll 4
            for (int s = 0; s < CHUNK; ++s) {
                float2 u = sx[row][s];
                float hu1 = 0.5f * u.x;
                float zib = fmaf(u.x, p.kibu, p.cib);
                float zl  = fmaf(u.y, p.kol, p.col);
                float ol  = fmaf(tanha(zl), p.hol1, p.hol1);
                float zo  = fmaf(c, p.koo, p.coo);
                float zi  = fmaf(c, p.kib, zib);
                float to  = tanha(zo);
                float ti  = tanha(zi);
                float hc  = p.hoo1 * c;
                bool  cpos = (c > 0.0f);
                float olc_c = ol * c;
                float L   = cpos ? fminf(olc_c, u.y) : olc_c;
                float olc = cpos ? fminf(ol, __fdividef(u.y, c)) : ol;
                float base = ((c - hc) + hu1) - L;
                sc[lane][s]   = c;                           // pre-update state
                soo[lane][s]  = fmaf(to, p.hoo1, p.hoo1);
                sib[lane][s]  = fmaf(ti, 0.5f, 0.5f);
                sol[lane][s]  = ol;
                solc[lane][s] = olc;
                c = fmaf(-hu1, ti, fmaf(-hc, to, base));
            }
        }
    }
    __syncthreads();

    // ---- phase 3: all 256 threads sweep 4 consecutive timesteps each ----
    const int i0 = tid * 4;                       // 0..1020 within block
    const int t  = blockIdx.x * (CPB * CHUNK) + i0;
    if (t >= B_TOT) return;
    const int r  = i0 >> 5;                       // chunk row
    const int s0 = i0 & 31;

    const int tl   = time_lag_p[0];
    const float os = s_os;
    const size_t B = (size_t)B_TOT;

    float4 vh, vc, vl, vlc, vbp, vib, voo, vol, volc, vf, vos;
    float* ph = &vh.x;  float* pc = &vc.x;  float* pl = &vl.x;  float* plc = &vlc.x;
    float* pbp = &vbp.x; float* pib = &vib.x; float* poo = &voo.x;
    float* pol = &vol.x; float* polc = &volc.x; float* pf = &vf.x; float* pos = &vos.x;

    #pragma unroll
    for (int k = 0; k < 4; ++k) {
        int s = s0 + k;
        float cv  = sc[r][s];
        float oo  = soo[r][s];
        float ib  = sib[r][s];
        float ol  = sol[r][s];
        float olc = solc[r][s];
        float2 u  = sx[r + WARMCH][s];
        float m   = (t + k >= tl) ? 1.0f : 0.0f;
        float bp  = ib * u.x;
        float h   = fmaf(oo, cv, bp);
        ph[k]   = m * h;
        pc[k]   = m * cv;
        pl[k]   = m * (ol * cv);
        plc[k]  = m * (olc * cv);
        pbp[k]  = m * bp;
        pib[k]  = m * ib;
        poo[k]  = m * oo;
        pol[k]  = m * ol;
        polc[k] = m * olc;
        pf[k]   = m * (1.0f - oo - olc);
        pos[k]  = m * os;
    }

    *reinterpret_cast<float4*>(out + t)          = vh;
    *reinterpret_cast<float4*>(out + B + t)      = vc;
    *reinterpret_cast<float4*>(out + 2 * B + t)  = vl;
    *reinterpret_cast<float4*>(out + 3 * B + t)  = vlc;
    *reinterpret_cast<float4*>(out + 4 * B + t)  = vbp;
    *reinterpret_cast<float4*>(out + 5 * B + t)  = vib;
    *reinterpret_cast<float4*>(out + 6 * B + t)  = voo;
    *reinterpret_cast<float4*>(out + 7 * B + t)  = vol;
    *reinterpret_cast<float4*>(out + 8 * B + t)  = volc;
    *reinterpret_cast<float4*>(out + 9 * B + t)  = vf;
    *reinterpret_cast<float4*>(out + 10 * B + 2 * (size_t)t) =
        make_float4(ph[0], pos[0], ph[1], pos[1]);
    *reinterpret_cast<float4*>(out + 10 * B + 2 * (size_t)t + 4) =
        make_float4(ph[2], pos[2], ph[3], pos[3]);
    *reinterpret_cast<float4*>(out + 12 * B + t) = vos;
}

// ---------------- launch ----------------
extern "C" void kernel_launch(void* const* d_in, const int* in_sizes, int n_in,
                              void* d_out, int out_size) {
    const float4* x4    = (const float4*)d_in[0];
    const int*    tl    = (const int*)   d_in[2];
    const float*  y_obs = (const float*) d_in[3];
    const float*  cmean = (const float*) d_in[4];
    const float*  cstd  = (const float*) d_in[5];
    const float*  wro   = (const float*) d_in[6];
    const float*  wrl   = (const float*) d_in[7];
    const float*  wrf   = (const float*) d_in[8];
    const float*  b0o   = (const float*) d_in[9];
    const float*  wb1o  = (const float*) d_in[10];
    const float*  b0l   = (const float*) d_in[11];
    const float*  wb2l  = (const float*) d_in[12];
    const float*  wb1u  = (const float*) d_in[13];
    const float*  b0u   = (const float*) d_in[14];
    float* out = (float*)d_out;

    cudaFuncSetAttribute(fused_k, cudaFuncAttributeMaxDynamicSharedMemorySize,
                         SMEM_TOTAL);

    reduce_k<<<RBLOCKS, 256>>>(y_obs);

    fused_k<<<GRID, SBLK, SMEM_TOTAL>>>(x4, out, tl,
        cmean, cstd, wro, wrl, wrf, b0o, wb1o, b0l, wb2l, wb1u, b0u);
}

// round 8
// speedup vs baseline: 1.0912x; 1.0912x over previous
#include <cuda_runtime.h>
#include <math.h>

// ---------------- problem constants ----------------
constexpr int   B_TOT  = 1000000;
constexpr int   SPIN   = 1000;
constexpr int   TRAIN  = 800000;
constexpr float ML     = 2.9086f;
constexpr float SL     = 1.898f;
constexpr float U1MAX  = 221.519f;

// chunked-scan parameters
constexpr int CHUNK  = 32;                    // steps per chunk
constexpr int WARMCH = 2;                     // warm-up chunks (64 steps)
constexpr int NCH    = B_TOT / CHUNK;         // 31250
constexpr int SBLK   = 128;                   // threads per block (= chunks per scan block)
constexpr int SGRID  = (NCH + SBLK - 1) / SBLK;  // 245 scan blocks
constexpr int RBLK   = 132;                   // reduce blocks (first in grid)
constexpr int GRID   = RBLK + SGRID;          // 377 — fits one wave at >=2 blocks/SM
constexpr int ROWS   = SBLK + WARMCH;         // 130 window rows

// dynamic SMEM: x window + c trajectory (stride-33 padding, conflict-free)
constexpr int SX_BYTES   = ROWS * 33 * 8;     // 34320
constexpr int SC_BYTES   = SBLK * 33 * 4;     // 16896
constexpr int SMEM_TOTAL = SX_BYTES + SC_BYTES;  // 51216 -> up to 4 blocks/SM

__device__ double g_part[RBLK][2];
__device__ int    g_cnt = 0;   // reduce-blocks-done counter (reset each call)
__device__ int    g_fin = 0;   // all-blocks-done counter   (reset each call)

// ---------------- math helpers ----------------
__device__ __forceinline__ float tanha(float z) {
    float r;
    asm("tanh.approx.f32 %0, %1;" : "=f"(r) : "f"(z));
    return r;
}

struct P {
    float koo, coo;        // zo = koo*c + coo
    float kib, cib, kibu;  // zi = kib*c + (kibu*u1 + cib)
    float kol, col;        // zl = kol*u2 + col
    float hoo1, hol1;      // 0.5*oo1, 0.5*ol1
};

__device__ __forceinline__ P load_params(
    const float* cmean, const float* cstd,
    const float* wro, const float* wrl, const float* wrf,
    const float* b0o, const float* wb1o,
    const float* b0l, const float* wb2l,
    const float* wb1u, const float* b0u)
{
    P p;
    float mo = cmean[0];
    float inv_so = 1.0f / cstd[0];
    float eo = __expf(wro[0]);
    float el = __expf(wrl[0]);
    float ef = __expf(wrf[0]);
    float id = __fdividef(1.0f, eo + el + ef);
    p.hoo1 = 0.5f * eo * id;
    p.hol1 = 0.5f * el * id;
    float w1o = wb1o[0], w1u = wb1u[0], w2l = wb2l[0];
    p.koo  = 0.5f * w1o * inv_so;
    p.coo  = 0.5f * (b0o[0] - mo * inv_so * w1o);
    p.kib  = 0.5f * w1u * inv_so;
    p.cib  = 0.5f * (b0u[0] - mo * inv_so * w1u);
    p.kibu = 0.5f * w1u / U1MAX;
    p.kol  = 0.5f * w2l / SL;
    p.col  = 0.5f * (b0l[0] - (ML / SL) * w2l);
    return p;
}

// one recurrence step (state only). chain: fma -> tanh -> fma -> fma.
__device__ __forceinline__ float step_c(float c, float u1, float u2, const P& p) {
    float hu1 = 0.5f * u1;
    float zib = fmaf(u1, p.kibu, p.cib);
    float zl  = fmaf(u2, p.kol, p.col);
    float ol  = fmaf(tanha(zl), p.hol1, p.hol1);
    float zo  = fmaf(c, p.koo, p.coo);
    float zi  = fmaf(c, p.kib, zib);
    float to  = tanha(zo);
    float ti  = tanha(zi);
    float hc  = p.hoo1 * c;
    float olc_c = ol * c;
    float L   = (c > 0.0f) ? fminf(olc_c, u2) : olc_c;
    float base = ((c - hc) + hu1) - L;
    return fmaf(-hu1, ti, fmaf(-hc, to, base));
}

// sweep of 4 consecutive timesteps; MASKED selects the time_lag path
template <bool MASKED>
__device__ __forceinline__ void sweep_quad(
    const float* __restrict__ sc_row, const float2* __restrict__ sx_row,
    int s0, int t, int tl, float os, const P& p,
    float* __restrict__ out)
{
    const size_t B = (size_t)B_TOT;
    float4 vh, vc, vl, vlc, vbp, vib, voo, vol, volc, vf, vos;
    float* ph = &vh.x;  float* pc = &vc.x;  float* pl = &vl.x;  float* plc = &vlc.x;
    float* pbp = &vbp.x; float* pib = &vib.x; float* poo = &voo.x;
    float* pol = &vol.x; float* polc = &volc.x; float* pf = &vf.x; float* pos = &vos.x;

    #pragma unroll
    for (int k = 0; k < 4; ++k) {
        float cv  = sc_row[s0 + k];
        float2 u  = sx_row[s0 + k];
        float zo  = fmaf(cv, p.koo, p.coo);
        float zi  = fmaf(cv, p.kib, fmaf(u.x, p.kibu, p.cib));
        float zl  = fmaf(u.y, p.kol, p.col);
        float oo  = fmaf(tanha(zo), p.hoo1, p.hoo1);
        float ib  = fmaf(tanha(zi), 0.5f, 0.5f);
        float ol  = fmaf(tanha(zl), p.hol1, p.hol1);
        bool  cp  = (cv > 0.0f);
        float olc  = cp ? fminf(ol, __fdividef(u.y, cv)) : ol;
        float olcc = cp ? fminf(ol * cv, u.y) : ol * cv;
        float bp  = ib * u.x;
        float h   = fmaf(oo, cv, bp);
        float f   = 1.0f - oo - olc;
        if (MASKED) {
            float m = (t + k >= tl) ? 1.0f : 0.0f;
            ph[k] = m * h;   pc[k] = m * cv;       pl[k] = m * (ol * cv);
            plc[k] = m * olcc; pbp[k] = m * bp;    pib[k] = m * ib;
            poo[k] = m * oo; pol[k] = m * ol;      polc[k] = m * olc;
            pf[k] = m * f;   pos[k] = m * os;
        } else {
            ph[k] = h;       pc[k] = cv;           pl[k] = ol * cv;
            plc[k] = olcc;   pbp[k] = bp;          pib[k] = ib;
            poo[k] = oo;     pol[k] = ol;          polc[k] = olc;
            pf[k] = f;       pos[k] = os;
        }
    }
    *reinterpret_cast<float4*>(out + t)          = vh;
    *reinterpret_cast<float4*>(out + B + t)      = vc;
    *reinterpret_cast<float4*>(out + 2 * B + t)  = vl;
    *reinterpret_cast<float4*>(out + 3 * B + t)  = vlc;
    *reinterpret_cast<float4*>(out + 4 * B + t)  = vbp;
    *reinterpret_cast<float4*>(out + 5 * B + t)  = vib;
    *reinterpret_cast<float4*>(out + 6 * B + t)  = voo;
    *reinterpret_cast<float4*>(out + 7 * B + t)  = vol;
    *reinterpret_cast<float4*>(out + 8 * B + t)  = volc;
    *reinterpret_cast<float4*>(out + 9 * B + t)  = vf;
    *reinterpret_cast<float4*>(out + 10 * B + 2 * (size_t)t) =
        make_float4(ph[0], pos[0], ph[1], pos[1]);
    *reinterpret_cast<float4*>(out + 10 * B + 2 * (size_t)t + 4) =
        make_float4(ph[2], pos[2], ph[3], pos[3]);
    *reinterpret_cast<float4*>(out + 12 * B + t) = vos;
}

// ---------------- the single fused kernel ---------------------------------
__global__ __launch_bounds__(SBLK) void fused_k(
    const float4* __restrict__ x4,
    float* __restrict__ out,
    const int* __restrict__ time_lag_p,
    const float* __restrict__ y_obs,
    const float* cmean, const float* cstd,
    const float* wro, const float* wrl, const float* wrf,
    const float* b0o, const float* wb1o,
    const float* b0l, const float* wb2l,
    const float* wb1u, const float* b0u)
{
    const int tid = threadIdx.x;

    // ================= reduce blocks (first RBLK, resident in wave 1) ======
    if (blockIdx.x < RBLK) {
        __shared__ double shred[2][4];
        const float4* y4 = reinterpret_cast<const float4*>(y_obs + SPIN);
        const int n4 = (TRAIN - SPIN) / 4;
        double s = 0.0, s2 = 0.0;
        for (int i = blockIdx.x * SBLK + tid; i < n4; i += RBLK * SBLK) {
            float4 v = __ldg(y4 + i);
            double a = v.x, b = v.y, cc = v.z, d = v.w;
            s  += (a + b) + (cc + d);
            s2 += (a * a + b * b) + (cc * cc + d * d);
        }
        #pragma unroll
        for (int o = 16; o > 0; o >>= 1) {
            s  += __shfl_down_sync(0xffffffffu, s,  o);
            s2 += __shfl_down_sync(0xffffffffu, s2, o);
        }
        int lane = tid & 31, warp = tid >> 5;
        if (lane == 0) { shred[0][warp] = s; shred[1][warp] = s2; }
        __syncthreads();
        if (tid == 0) {
            s  = shred[0][0] + shred[0][1] + shred[0][2] + shred[0][3];
            s2 = shred[1][0] + shred[1][1] + shred[1][2] + shred[1][3];
            g_part[blockIdx.x][0] = s;
            g_part[blockIdx.x][1] = s2;
            __threadfence();
            atomicAdd(&g_cnt, 1);
            // completion bookkeeping (reset for next graph replay)
            int r = atomicAdd(&g_fin, 1);
            if (r == GRID - 1) { g_cnt = 0; g_fin = 0; }
        }
        return;
    }

    // ================= scan + sweep blocks =================================
    extern __shared__ char smem_raw[];
    float2 (*sx)[33] = reinterpret_cast<float2(*)[33]>(smem_raw);
    float  (*sc)[33] = reinterpret_cast<float(*)[33]>(smem_raw + SX_BYTES);
    __shared__ float s_os;

    const int rb = blockIdx.x - RBLK;
    const int b0 = rb * SBLK;                     // first chunk of this block
    const int base_t = (b0 - WARMCH) * CHUNK;     // window start (may be < 0)

    const P p = load_params(cmean, cstd, wro, wrl, wrf, b0o, wb1o, b0l, wb2l, wb1u, b0u);

    // ---- stage input window (coalesced float4) ----
    constexpr int NLD4 = ROWS * CHUNK / 2;        // 2080
    #pragma unroll 4
    for (int i = tid; i < NLD4; i += SBLK) {
        int t = base_t + 2 * i;
        float4 v = make_float4(0.f, 0.f, 0.f, 0.f);
        if (t >= 0 && t < B_TOT) v = __ldg(x4 + (t >> 1));
        int li = 2 * i;
        int row = li >> 5, s = li & 31;
        sx[row][s]     = make_float2(v.x, v.y);
        sx[row][s + 1] = make_float2(v.z, v.w);
    }
    __syncthreads();

    // ---- recurrence: thread = chunk; record pre-update state into sc ----
    const int chunk = b0 + tid;
    const int row   = tid + WARMCH;
    if (chunk < NCH) {
        float c = 0.0f;
        #pragma unroll
        for (int d = WARMCH; d >= 1; --d) {
            if (chunk - d >= 0) {
                #pragma unroll 8
                for (int s = 0; s < CHUNK; ++s) {
                    float2 u = sx[row - d][s];
                    c = step_c(c, u.x, u.y, p);
                }
            }
        }
        #pragma unroll 8
        for (int s = 0; s < CHUNK; ++s) {
            sc[tid][s] = c;
            float2 u = sx[row][s];
            c = step_c(c, u.x, u.y, p);
        }
    }

    // ---- obsstd: warp 0 waits for reduce blocks (all co-resident) & folds --
    if (tid < 32) {
        if (tid == 0) {
            while (*(volatile int*)&g_cnt < RBLK) { }
            __threadfence();
        }
        __syncwarp();
        double s = 0.0, s2 = 0.0;
        for (int i = tid; i < RBLK; i += 32) {
            s  += g_part[i][0];
            s2 += g_part[i][1];
        }
        #pragma unroll
        for (int o = 16; o > 0; o >>= 1) {
            s  += __shfl_down_sync(0xffffffffu, s,  o);
            s2 += __shfl_down_sync(0xffffffffu, s2, o);
        }
        if (tid == 0) {
            double n = (double)(TRAIN - SPIN);
            s_os = (float)sqrt((s2 - s * s / n) / (n - 1.0));
        }
    }
    __syncthreads();

    // ---- sweep: 8 iterations x 4 consecutive timesteps per thread ----
    const int tl   = time_lag_p[0];
    const float os = s_os;
    const int t_blk = b0 * CHUNK;                 // block's first timestep
    const bool nomask = (tl <= t_blk);

    #pragma unroll
    for (int j = 0; j < 8; ++j) {
        int i = j * (SBLK * 4) + tid * 4;         // 0..4095
        int t = t_blk + i;
        if (t >= B_TOT) break;
        int r = i >> 5, s0 = i & 31;
        if (nomask)
            sweep_quad<false>(sc[r], sx[r + WARMCH], s0, t, tl, os, p, out);
        else
            sweep_quad<true>(sc[r], sx[r + WARMCH], s0, t, tl, os, p, out);
    }

    // ---- completion bookkeeping (reset counters for next replay) ----
    if (tid == 0) {
        int r = atomicAdd(&g_fin, 1);
        if (r == GRID - 1) { g_cnt = 0; g_fin = 0; }
    }
}

// ---------------- launch ----------------
extern "C" void kernel_launch(void* const* d_in, const int* in_sizes, int n_in,
                              void* d_out, int out_size) {
    const float4* x4    = (const float4*)d_in[0];
    const int*    tl    = (const int*)   d_in[2];
    const float*  y_obs = (const float*) d_in[3];
    const float*  cmean = (const float*) d_in[4];
    const float*  cstd  = (const float*) d_in[5];
    const float*  wro   = (const float*) d_in[6];
    const float*  wrl   = (const float*) d_in[7];
    const float*  wrf   = (const float*) d_in[8];
    const float*  b0o   = (const float*) d_in[9];
    const float*  wb1o  = (const float*) d_in[10];
    const float*  b0l   = (const float*) d_in[11];
    const float*  wb2l  = (const float*) d_in[12];
    const float*  wb1u  = (const float*) d_in[13];
    const float*  b0u   = (const float*) d_in[14];
    float* out = (float*)d_out;

    cudaFuncSetAttribute(fused_k, cudaFuncAttributeMaxDynamicSharedMemorySize,
                         SMEM_TOTAL);

    fused_k<<<GRID, SBLK, SMEM_TOTAL>>>(x4, out, tl, y_obs,
        cmean, cstd, wro, wrl, wrf, b0o, wb1o, b0l, wb2l, wb1u, b0u);
}

// round 9
// speedup vs baseline: 1.2875x; 1.1799x over previous
#include <cuda_runtime.h>
#include <math.h>

// ---------------- problem constants ----------------
constexpr int   B_TOT  = 1000000;
constexpr int   SPIN   = 1000;
constexpr int   TRAIN  = 800000;
constexpr float ML     = 2.9086f;
constexpr float SL     = 1.898f;
constexpr float U1MAX  = 221.519f;

// chunked-scan parameters
constexpr int CHUNK   = 32;                   // steps per chunk
constexpr int WARMCH  = 2;                    // warm-up chunks (64 steps)
constexpr int NCH     = B_TOT / CHUNK;        // 31250 (exact)
constexpr int SBLK    = 128;                  // threads (=chunks) per scan block
constexpr int SGRID   = (NCH + SBLK - 1) / SBLK;   // 245

constexpr int RBLOCKS = 132;
__device__ double g_part[RBLOCKS][2];

// ---------------- math helpers ----------------
__device__ __forceinline__ float tanha(float z) {
    float r;
    asm("tanh.approx.f32 %0, %1;" : "=f"(r) : "f"(z));
    return r;
}

struct P {
    float koo, coo;        // zo = koo*c + coo
    float kib, cib, kibu;  // zi = kib*c + (kibu*u1 + cib)
    float kol, col;        // zl = kol*u2 + col
    float hoo1, hol1;      // 0.5*oo1, 0.5*ol1
};

__device__ __forceinline__ P load_params(
    const float* cmean, const float* cstd,
    const float* wro, const float* wrl, const float* wrf,
    const float* b0o, const float* wb1o,
    const float* b0l, const float* wb2l,
    const float* wb1u, const float* b0u)
{
    P p;
    float mo = cmean[0];
    float inv_so = 1.0f / cstd[0];
    float eo = __expf(wro[0]);
    float el = __expf(wrl[0]);
    float ef = __expf(wrf[0]);
    float id = __fdividef(1.0f, eo + el + ef);
    p.hoo1 = 0.5f * eo * id;
    p.hol1 = 0.5f * el * id;
    float w1o = wb1o[0], w1u = wb1u[0], w2l = wb2l[0];
    p.koo  = 0.5f * w1o * inv_so;
    p.coo  = 0.5f * (b0o[0] - mo * inv_so * w1o);
    p.kib  = 0.5f * w1u * inv_so;
    p.cib  = 0.5f * (b0u[0] - mo * inv_so * w1u);
    p.kibu = 0.5f * w1u / U1MAX;
    p.kol  = 0.5f * w2l / SL;
    p.col  = 0.5f * (b0l[0] - (ML / SL) * w2l);
    return p;
}

// one recurrence step (state only). chain: fma -> tanh -> fma -> fma.
__device__ __forceinline__ float step_c(float c, float u1, float u2, const P& p) {
    float hu1 = 0.5f * u1;
    float zib = fmaf(u1, p.kibu, p.cib);
    float zl  = fmaf(u2, p.kol, p.col);
    float ol  = fmaf(tanha(zl), p.hol1, p.hol1);
    float zo  = fmaf(c, p.koo, p.coo);
    float zi  = fmaf(c, p.kib, zib);
    float to  = tanha(zo);
    float ti  = tanha(zi);
    float hc  = p.hoo1 * c;
    float olc_c = ol * c;
    float L   = (c > 0.0f) ? fminf(olc_c, u2) : olc_c;
    float base = ((c - hc) + hu1) - L;
    return fmaf(-hu1, ti, fmaf(-hc, to, base));
}

// ---------------- kernel A: fused scan + reduction partials ---------------
__global__ __launch_bounds__(SBLK) void scanreduce_k(
    const float4* __restrict__ x4,
    float* __restrict__ c_out,
    const float* __restrict__ y_obs,
    const float* cmean, const float* cstd,
    const float* wro, const float* wrl, const float* wrf,
    const float* b0o, const float* wb1o,
    const float* b0l, const float* wb2l,
    const float* wb1u, const float* b0u)
{
    __shared__ float2 sx[SBLK + WARMCH][CHUNK + 1];   // 130 x 33 float2 = 34.3KB
    __shared__ double shred[2][SBLK / 32];

    const int tid = threadIdx.x;

    if (blockIdx.x >= SGRID) {
        // ---------------- reduction branch ----------------
        const int rbid = blockIdx.x - SGRID;
        const float4* y4 = reinterpret_cast<const float4*>(y_obs + SPIN);
        const int n4 = (TRAIN - SPIN) / 4;
        double s = 0.0, s2 = 0.0;
        int stride = RBLOCKS * SBLK;
        for (int i = rbid * SBLK + tid; i < n4; i += stride) {
            float4 v = __ldg(y4 + i);
            double a = v.x, b = v.y, cc = v.z, d = v.w;
            s  += (a + b) + (cc + d);
            s2 += (a * a + b * b) + (cc * cc + d * d);
        }
        #pragma unroll
        for (int o = 16; o > 0; o >>= 1) {
            s  += __shfl_down_sync(0xffffffffu, s,  o);
            s2 += __shfl_down_sync(0xffffffffu, s2, o);
        }
        int lane = tid & 31, warp = tid >> 5;
        if (lane == 0) { shred[0][warp] = s; shred[1][warp] = s2; }
        __syncthreads();
        if (warp == 0) {
            s  = (lane < SBLK / 32) ? shred[0][lane] : 0.0;
            s2 = (lane < SBLK / 32) ? shred[1][lane] : 0.0;
            #pragma unroll
            for (int o = 2; o > 0; o >>= 1) {
                s  += __shfl_down_sync(0xffffffffu, s,  o);
                s2 += __shfl_down_sync(0xffffffffu, s2, o);
            }
            if (lane == 0) { g_part[rbid][0] = s; g_part[rbid][1] = s2; }
        }
        return;
    }

    // ---------------- scan branch ----------------
    const int b0  = blockIdx.x * SBLK;                 // first owned chunk
    const int base_t = (b0 - WARMCH) * CHUNK;          // window start (may be <0)

    const P p = load_params(cmean, cstd, wro, wrl, wrf, b0o, wb1o, b0l, wb2l, wb1u, b0u);

    // stage window: (SBLK+WARMCH)*CHUNK timesteps, 2 per float4
    constexpr int NLD4 = (SBLK + WARMCH) * CHUNK / 2;  // 2080
    #pragma unroll 4
    for (int i = tid; i < NLD4; i += SBLK) {
        int t = base_t + 2 * i;
        float4 v = make_float4(0.f, 0.f, 0.f, 0.f);
        if (t >= 0 && t < B_TOT) v = __ldg(x4 + (t >> 1));
        int li = 2 * i;                                // local timestep
        int row = li >> 5, s = li & 31;
        sx[row][s]     = make_float2(v.x, v.y);
        sx[row][s + 1] = make_float2(v.z, v.w);
    }
    __syncthreads();

    // recurrence
    const int chunk = b0 + tid;
    const int row   = tid + WARMCH;                    // own SMEM row
    float c = 0.0f;
    if (chunk < NCH) {
        #pragma unroll
        for (int d = WARMCH; d >= 1; --d) {
            if (chunk - d >= 0) {
                #pragma unroll 8
                for (int s = 0; s < CHUNK; ++s) {
                    float2 u = sx[row - d][s];
                    c = step_c(c, u.x, u.y, p);
                }
            }
        }
        #pragma unroll 8
        for (int s = 0; s < CHUNK; ++s) {
            float2 u = sx[row][s];
            sx[row][s].x = c;                          // record pre-update state
            c = step_c(c, u.x, u.y, p);
        }
    }
    __syncthreads();

    // coalesced write-back of c trajectory
    const int t0 = b0 * CHUNK;
    #pragma unroll 4
    for (int i = tid; i < SBLK * CHUNK; i += SBLK) {
        int t = t0 + i;
        if (t < B_TOT) c_out[t] = sx[(i >> 5) + WARMCH][i & 31].x;
    }
}

// ---------------- kernel B: pointwise outputs, 2 timesteps/thread ---------
__global__ __launch_bounds__(256) void point_k(
    const float4* __restrict__ x4,        // x as float4: exactly 2 timesteps
    float* __restrict__ out,
    const int* __restrict__ time_lag_p,
    const float* cmean, const float* cstd,
    const float* wro, const float* wrl, const float* wrf,
    const float* b0o, const float* wb1o,
    const float* b0l, const float* wb2l,
    const float* wb1u, const float* b0u)
{
    __shared__ float s_os;

    // warp 0: fold the RBLOCKS partials into obsstd (ddof=1)
    if (threadIdx.x < 32) {
        int lane = threadIdx.x;
        double s = 0.0, s2 = 0.0;
        for (int i = lane; i < RBLOCKS; i += 32) {
            s  += g_part[i][0];
            s2 += g_part[i][1];
        }
        #pragma unroll
        for (int o = 16; o > 0; o >>= 1) {
            s  += __shfl_down_sync(0xffffffffu, s,  o);
            s2 += __shfl_down_sync(0xffffffffu, s2, o);
        }
        if (lane == 0) {
            double n = (double)(TRAIN - SPIN);
            s_os = (float)sqrt((s2 - s * s / n) / (n - 1.0));
        }
    }

    int i = blockIdx.x * blockDim.x + threadIdx.x;     // pair index
    bool act = (i < B_TOT / 2);

    const P p = load_params(cmean, cstd, wro, wrl, wrf, b0o, wb1o, b0l, wb2l, wb1u, b0u);
    const int tl = time_lag_p[0];
    const size_t B = (size_t)B_TOT;

    // hoisted loads: one float2 (c pair) + one float4 (x pair)
    float2 c2 = make_float2(0.f, 0.f);
    float4 xa = make_float4(0.f, 0.f, 0.f, 0.f);
    if (act) {
        c2 = __ldg(reinterpret_cast<const float2*>(out + B) + i);
        xa = __ldg(x4 + i);
    }

    __syncthreads();
    const float os = s_os;
    if (!act) return;

    float cv[2]  = {c2.x, c2.y};
    float u1v[2] = {xa.x, xa.z};
    float u2v[2] = {xa.y, xa.w};

    float2 vh, vc, vl, vlc, vbp, vib, voo, vol, volc, vf, vos;
    float* ph = &vh.x;  float* pc = &vc.x;  float* pl = &vl.x;  float* plc = &vlc.x;
    float* pbp = &vbp.x; float* pib = &vib.x; float* poo = &voo.x;
    float* pol = &vol.x; float* polc = &volc.x; float* pf = &vf.x; float* pos = &vos.x;

    int t0 = 2 * i;
    #pragma unroll
    for (int j = 0; j < 2; ++j) {
        float c = cv[j], u1 = u1v[j], u2 = u2v[j];
        float zo = fmaf(c, p.koo, p.coo);
        float zi = fmaf(c, p.kib, fmaf(u1, p.kibu, p.cib));
        float zl = fmaf(u2, p.kol, p.col);
        float oo = fmaf(tanha(zo), p.hoo1, p.hoo1);
        float ib = fmaf(tanha(zi), 0.5f, 0.5f);
        float ol = fmaf(tanha(zl), p.hol1, p.hol1);
        bool  cp = (c > 0.0f);
        float olc  = cp ? fminf(ol, __fdividef(u2, c)) : ol;
        float olcc = cp ? fminf(ol * c, u2) : ol * c;
        float f   = 1.0f - oo - olc;
        float m   = (t0 + j >= tl) ? 1.0f : 0.0f;
        float bp  = ib * u1;
        float h   = fmaf(oo, c, bp);
        ph[j]   = m * h;
        pc[j]   = m * c;
        pl[j]   = m * (ol * c);
        plc[j]  = m * olcc;
        pbp[j]  = m * bp;
        pib[j]  = m * ib;
        poo[j]  = m * oo;
        pol[j]  = m * ol;
        polc[j] = m * olc;
        pf[j]   = m * f;
        pos[j]  = m * os;
    }

    reinterpret_cast<float2*>(out)[i]          = vh;
    reinterpret_cast<float2*>(out + B)[i]      = vc;
    reinterpret_cast<float2*>(out + 2 * B)[i]  = vl;
    reinterpret_cast<float2*>(out + 3 * B)[i]  = vlc;
    reinterpret_cast<float2*>(out + 4 * B)[i]  = vbp;
    reinterpret_cast<float2*>(out + 5 * B)[i]  = vib;
    reinterpret_cast<float2*>(out + 6 * B)[i]  = voo;
    reinterpret_cast<float2*>(out + 7 * B)[i]  = vol;
    reinterpret_cast<float2*>(out + 8 * B)[i]  = volc;
    reinterpret_cast<float2*>(out + 9 * B)[i]  = vf;
    reinterpret_cast<float4*>(out + 10 * B)[i] =
        make_float4(ph[0], pos[0], ph[1], pos[1]);     // interleaved h_nout pair
    reinterpret_cast<float2*>(out + 12 * B)[i] = vos;
}

// ---------------- launch ----------------
extern "C" void kernel_launch(void* const* d_in, const int* in_sizes, int n_in,
                              void* d_out, int out_size) {
    const float4* x4    = (const float4*)d_in[0];
    const int*    tl    = (const int*)   d_in[2];
    const float*  y_obs = (const float*) d_in[3];
    const float*  cmean = (const float*) d_in[4];
    const float*  cstd  = (const float*) d_in[5];
    const float*  wro   = (const float*) d_in[6];
    const float*  wrl   = (const float*) d_in[7];
    const float*  wrf   = (const float*) d_in[8];
    const float*  b0o   = (const float*) d_in[9];
    const float*  wb1o  = (const float*) d_in[10];
    const float*  b0l   = (const float*) d_in[11];
    const float*  wb2l  = (const float*) d_in[12];
    const float*  wb1u  = (const float*) d_in[13];
    const float*  b0u   = (const float*) d_in[14];
    float* out = (float*)d_out;

    float* c_out = out + (size_t)B_TOT;                   // stash c in c_n slot
    scanreduce_k<<<SGRID + RBLOCKS, SBLK>>>(x4, c_out, y_obs,
        cmean, cstd, wro, wrl, wrf, b0o, wb1o, b0l, wb2l, wb1u, b0u);

    point_k<<<(B_TOT / 2 + 255) / 256, 256>>>(
        x4, out, tl,
        cmean, cstd, wro, wrl, wrf, b0o, wb1o, b0l, wb2l, wb1u, b0u);
}